// round 1
// baseline (speedup 1.0000x reference)
#include <cuda_runtime.h>

#define TT 8192
#define DD 64
#define BT 64
#define PAD 68      // padded row stride (floats) for X tiles
#define PADP 136    // padded row stride for duplicated P tile
#define NT (TT / BT)

typedef unsigned long long f2;

__device__ __forceinline__ void fma2(f2& d, f2 a, f2 b) {
    asm("fma.rn.f32x2 %0, %1, %2, %0;" : "+l"(d) : "l"(a), "l"(b));
}
__device__ __forceinline__ float2 f2unpack(f2 v) {
    float2 f;
    asm("mov.b64 {%0, %1}, %2;" : "=f"(f.x), "=f"(f.y) : "l"(v));
    return f;
}
__device__ __forceinline__ f2 f2dup(float x) {
    f2 r;
    asm("mov.b64 %0, {%1, %1};" : "=l"(r) : "f"(x));
    return r;
}
__device__ __forceinline__ float f2hadd(f2 v) {
    float2 f = f2unpack(v);
    return f.x + f.y;
}

// scratch: c_j = m_j + ln(l_j) per (batch, j)
__device__ float g_c[2 * TT];

// ---------------------------------------------------------------------------
// Kernel 1: per-column softmax stats via row-wise pass (S symmetric).
// Each block: 64 rows of S (= 64 j's), sweeps all 8192 columns in 64-wide tiles.
// ---------------------------------------------------------------------------
__global__ void __launch_bounds__(256, 2) stats_kernel(const float* __restrict__ x) {
    __shared__ float XI[BT * PAD];
    __shared__ float XJ[BT * PAD];
    const int b   = blockIdx.y;
    const int it  = blockIdx.x;
    const float* xb = x + (size_t)b * TT * DD;
    const int tid = threadIdx.x;
    const int g   = tid >> 4, l16 = tid & 15;
    const int i0  = g * 4;

#pragma unroll
    for (int k = 0; k < 4; k++) {
        int idx = tid + k * 256;
        int r = idx >> 4, c4 = (idx & 15) * 4;
        *(float4*)&XI[r * PAD + c4] = *(const float4*)&xb[(it * BT + r) * DD + c4];
    }

    float m[4], l[4];
#pragma unroll
    for (int r = 0; r < 4; r++) { m[r] = -1e30f; l[r] = 0.f; }

    for (int jt = 0; jt < NT; jt++) {
        __syncthreads();
#pragma unroll
        for (int k = 0; k < 4; k++) {
            int idx = tid + k * 256;
            int r = idx >> 4, c4 = (idx & 15) * 4;
            *(float4*)&XJ[r * PAD + c4] = *(const float4*)&xb[(jt * BT + r) * DD + c4];
        }
        __syncthreads();

        f2 acc[4][4];
#pragma unroll
        for (int r = 0; r < 4; r++)
#pragma unroll
            for (int c = 0; c < 4; c++) acc[r][c] = 0ull;

#pragma unroll
        for (int d = 0; d < DD; d += 4) {
            ulonglong2 av[4], bv[4];
#pragma unroll
            for (int r = 0; r < 4; r++)
                av[r] = *(const ulonglong2*)&XI[(i0 + r) * PAD + d];
#pragma unroll
            for (int c = 0; c < 4; c++)
                bv[c] = *(const ulonglong2*)&XJ[(l16 + 16 * c) * PAD + d];
#pragma unroll
            for (int r = 0; r < 4; r++)
#pragma unroll
                for (int c = 0; c < 4; c++) {
                    fma2(acc[r][c], av[r].x, bv[c].x);
                    fma2(acc[r][c], av[r].y, bv[c].y);
                }
        }

#pragma unroll
        for (int r = 0; r < 4; r++) {
            float s0 = f2hadd(acc[r][0]);
            float s1 = f2hadd(acc[r][1]);
            float s2 = f2hadd(acc[r][2]);
            float s3 = f2hadd(acc[r][3]);
            float mt = fmaxf(fmaxf(s0, s1), fmaxf(s2, s3));
#pragma unroll
            for (int w = 1; w < 16; w <<= 1)
                mt = fmaxf(mt, __shfl_xor_sync(0xffffffffu, mt, w));
            float nm = fmaxf(m[r], mt);
            float sum = __expf(s0 - nm) + __expf(s1 - nm) +
                        __expf(s2 - nm) + __expf(s3 - nm);
#pragma unroll
            for (int w = 1; w < 16; w <<= 1)
                sum += __shfl_xor_sync(0xffffffffu, sum, w);
            l[r] = l[r] * __expf(m[r] - nm) + sum;
            m[r] = nm;
        }
    }

    if (l16 == 0) {
#pragma unroll
        for (int r = 0; r < 4; r++)
            g_c[b * TT + it * BT + i0 + r] = m[r] + __logf(l[r]);
    }
}

// ---------------------------------------------------------------------------
// Kernel 2: out[i,d] = sum_j exp(S[i,j] - c_j) * x[j,d], output as [B, D, T].
// ---------------------------------------------------------------------------
__global__ void __launch_bounds__(256, 2) out_kernel(const float* __restrict__ x,
                                                     float* __restrict__ out) {
    extern __shared__ float sm[];
    float* XI = sm;                               // BT*PAD
    float* XJ = sm + BT * PAD;                    // BT*PAD
    float* P2 = sm + 2 * BT * PAD;                // BT*PADP (P duplicated pairs)
    float* CV = sm + 2 * BT * PAD + BT * PADP;    // 64

    const int b   = blockIdx.y;
    const int it  = blockIdx.x;
    const float* xb = x + (size_t)b * TT * DD;
    const int tid = threadIdx.x;
    const int g   = tid >> 4, l16 = tid & 15;
    const int i0  = g * 4;
    const int d0  = l16 * 4;

#pragma unroll
    for (int k = 0; k < 4; k++) {
        int idx = tid + k * 256;
        int r = idx >> 4, c4 = (idx & 15) * 4;
        *(float4*)&XI[r * PAD + c4] = *(const float4*)&xb[(it * BT + r) * DD + c4];
    }

    f2 o[4][2];
#pragma unroll
    for (int r = 0; r < 4; r++) { o[r][0] = 0ull; o[r][1] = 0ull; }

    for (int jt = 0; jt < NT; jt++) {
        __syncthreads();  // previous PV done reading XJ/P2
#pragma unroll
        for (int k = 0; k < 4; k++) {
            int idx = tid + k * 256;
            int r = idx >> 4, c4 = (idx & 15) * 4;
            *(float4*)&XJ[r * PAD + c4] = *(const float4*)&xb[(jt * BT + r) * DD + c4];
        }
        if (tid < 16)
            *(float4*)&CV[tid * 4] = *(const float4*)&g_c[b * TT + jt * BT + tid * 4];
        __syncthreads();

        // S tile
        f2 acc[4][4];
#pragma unroll
        for (int r = 0; r < 4; r++)
#pragma unroll
            for (int c = 0; c < 4; c++) acc[r][c] = 0ull;

#pragma unroll
        for (int d = 0; d < DD; d += 4) {
            ulonglong2 av[4], bv[4];
#pragma unroll
            for (int r = 0; r < 4; r++)
                av[r] = *(const ulonglong2*)&XI[(i0 + r) * PAD + d];
#pragma unroll
            for (int c = 0; c < 4; c++)
                bv[c] = *(const ulonglong2*)&XJ[(l16 + 16 * c) * PAD + d];
#pragma unroll
            for (int r = 0; r < 4; r++)
#pragma unroll
                for (int c = 0; c < 4; c++) {
                    fma2(acc[r][c], av[r].x, bv[c].x);
                    fma2(acc[r][c], av[r].y, bv[c].y);
                }
        }

        // P = exp(S - c_j), stored duplicated (p,p) for packed PV
#pragma unroll
        for (int r = 0; r < 4; r++)
#pragma unroll
            for (int c = 0; c < 4; c++) {
                int jc = l16 + 16 * c;
                float p = __expf(f2hadd(acc[r][c]) - CV[jc]);
                *(f2*)&P2[(i0 + r) * PADP + 2 * jc] = f2dup(p);
            }
        __syncthreads();

        // O += P @ XJ  (packed along d-pairs)
#pragma unroll 4
        for (int j = 0; j < BT; j += 4) {
            ulonglong2 xv[4];
#pragma unroll
            for (int q = 0; q < 4; q++)
                xv[q] = *(const ulonglong2*)&XJ[(j + q) * PAD + d0];
#pragma unroll
            for (int r = 0; r < 4; r++) {
                ulonglong2 u0 = *(const ulonglong2*)&P2[(i0 + r) * PADP + 2 * j];
                ulonglong2 u1 = *(const ulonglong2*)&P2[(i0 + r) * PADP + 2 * j + 4];
                fma2(o[r][0], u0.x, xv[0].x); fma2(o[r][1], u0.x, xv[0].y);
                fma2(o[r][0], u0.y, xv[1].x); fma2(o[r][1], u0.y, xv[1].y);
                fma2(o[r][0], u1.x, xv[2].x); fma2(o[r][1], u1.x, xv[2].y);
                fma2(o[r][0], u1.y, xv[3].x); fma2(o[r][1], u1.y, xv[3].y);
            }
        }
    }

    // transpose epilogue: [i,d] -> [d,i] through smem, coalesced store
    __syncthreads();
    float* Ot = P2;  // reuse, logical stride 65
#pragma unroll
    for (int r = 0; r < 4; r++) {
        float2 a = f2unpack(o[r][0]);
        float2 c = f2unpack(o[r][1]);
        Ot[(d0 + 0) * 65 + i0 + r] = a.x;
        Ot[(d0 + 1) * 65 + i0 + r] = a.y;
        Ot[(d0 + 2) * 65 + i0 + r] = c.x;
        Ot[(d0 + 3) * 65 + i0 + r] = c.y;
    }
    __syncthreads();
    float* ob = out + (size_t)b * DD * TT + it * BT;
#pragma unroll
    for (int k = 0; k < 4; k++) {
        int idx = tid + k * 256;
        int d = idx >> 4, q4 = (idx & 15) * 4;
        float4 v = make_float4(Ot[d * 65 + q4 + 0], Ot[d * 65 + q4 + 1],
                               Ot[d * 65 + q4 + 2], Ot[d * 65 + q4 + 3]);
        *(float4*)&ob[(size_t)d * TT + q4] = v;
    }
}

extern "C" void kernel_launch(void* const* d_in, const int* in_sizes, int n_in,
                              void* d_out, int out_size) {
    (void)in_sizes; (void)n_in; (void)out_size;
    const float* x = (const float*)d_in[0];
    float* out = (float*)d_out;

    const int smem2 = (2 * BT * PAD + BT * PADP + 64) * (int)sizeof(float);  // 69888 B
    cudaFuncSetAttribute(out_kernel, cudaFuncAttributeMaxDynamicSharedMemorySize, smem2);

    dim3 grid(NT, 2);
    stats_kernel<<<grid, 256>>>(x);
    out_kernel<<<grid, 256, smem2>>>(x, out);
}

// round 2
// speedup vs baseline: 1.6682x; 1.6682x over previous
#include <cuda_runtime.h>

#define TT 8192
#define DD 64
#define BT 64
#define PAD 68      // padded row stride (floats) for X tiles
#define PADP 136    // padded row stride for duplicated P tile
#define NT (TT / BT)

typedef unsigned long long f2;

__device__ __forceinline__ void fma2(f2& d, f2 a, f2 b) {
    asm("fma.rn.f32x2 %0, %1, %2, %0;" : "+l"(d) : "l"(a), "l"(b));
}
__device__ __forceinline__ float2 f2unpack(f2 v) {
    float2 f;
    asm("mov.b64 {%0, %1}, %2;" : "=f"(f.x), "=f"(f.y) : "l"(v));
    return f;
}
__device__ __forceinline__ f2 f2dup(float x) {
    f2 r;
    asm("mov.b64 %0, {%1, %1};" : "=l"(r) : "f"(x));
    return r;
}
__device__ __forceinline__ float f2hadd(f2 v) {
    float2 f = f2unpack(v);
    return f.x + f.y;
}

// scratch: c_j = m_j + ln(l_j) per (batch, j)
__device__ float g_c[2 * TT];

// ---------------------------------------------------------------------------
// Kernel 1: per-column softmax stats via row-wise pass (S symmetric).
// Each block: 64 rows of S (= 64 j's), sweeps all 8192 columns in 64-wide tiles.
// ---------------------------------------------------------------------------
__global__ void __launch_bounds__(256, 2) stats_kernel(const float* __restrict__ x) {
    __shared__ float XI[BT * PAD];
    __shared__ float XJ[BT * PAD];
    const int b   = blockIdx.y;
    const int it  = blockIdx.x;
    const float* xb = x + (size_t)b * TT * DD;
    const int tid = threadIdx.x;
    const int g   = tid >> 4, l16 = tid & 15;
    const int i0  = g * 4;

#pragma unroll
    for (int k = 0; k < 4; k++) {
        int idx = tid + k * 256;
        int r = idx >> 4, c4 = (idx & 15) * 4;
        *(float4*)&XI[r * PAD + c4] = *(const float4*)&xb[(it * BT + r) * DD + c4];
    }

    float m[4], l[4];
#pragma unroll
    for (int r = 0; r < 4; r++) { m[r] = -1e30f; l[r] = 0.f; }

    for (int jt = 0; jt < NT; jt++) {
        __syncthreads();
#pragma unroll
        for (int k = 0; k < 4; k++) {
            int idx = tid + k * 256;
            int r = idx >> 4, c4 = (idx & 15) * 4;
            *(float4*)&XJ[r * PAD + c4] = *(const float4*)&xb[(jt * BT + r) * DD + c4];
        }
        __syncthreads();

        f2 acc[4][4];
#pragma unroll
        for (int r = 0; r < 4; r++)
#pragma unroll
            for (int c = 0; c < 4; c++) acc[r][c] = 0ull;

#pragma unroll
        for (int d = 0; d < DD; d += 4) {
            ulonglong2 av[4], bv[4];
#pragma unroll
            for (int r = 0; r < 4; r++)
                av[r] = *(const ulonglong2*)&XI[(i0 + r) * PAD + d];
#pragma unroll
            for (int c = 0; c < 4; c++)
                bv[c] = *(const ulonglong2*)&XJ[(l16 + 16 * c) * PAD + d];
#pragma unroll
            for (int r = 0; r < 4; r++)
#pragma unroll
                for (int c = 0; c < 4; c++) {
                    fma2(acc[r][c], av[r].x, bv[c].x);
                    fma2(acc[r][c], av[r].y, bv[c].y);
                }
        }

#pragma unroll
        for (int r = 0; r < 4; r++) {
            float s0 = f2hadd(acc[r][0]);
            float s1 = f2hadd(acc[r][1]);
            float s2 = f2hadd(acc[r][2]);
            float s3 = f2hadd(acc[r][3]);
            float mt = fmaxf(fmaxf(s0, s1), fmaxf(s2, s3));
#pragma unroll
            for (int w = 1; w < 16; w <<= 1)
                mt = fmaxf(mt, __shfl_xor_sync(0xffffffffu, mt, w));
            float nm = fmaxf(m[r], mt);
            float sum = __expf(s0 - nm) + __expf(s1 - nm) +
                        __expf(s2 - nm) + __expf(s3 - nm);
#pragma unroll
            for (int w = 1; w < 16; w <<= 1)
                sum += __shfl_xor_sync(0xffffffffu, sum, w);
            l[r] = l[r] * __expf(m[r] - nm) + sum;
            m[r] = nm;
        }
    }

    if (l16 == 0) {
#pragma unroll
        for (int r = 0; r < 4; r++)
            g_c[b * TT + it * BT + i0 + r] = m[r] + __logf(l[r]);
    }
}

// ---------------------------------------------------------------------------
// Kernel 2: out[i,d] = sum_j exp(S[i,j] - c_j) * x[j,d], output as [B, D, T].
// ---------------------------------------------------------------------------
__global__ void __launch_bounds__(256, 2) out_kernel(const float* __restrict__ x,
                                                     float* __restrict__ out) {
    extern __shared__ float sm[];
    float* XI = sm;                               // BT*PAD
    float* XJ = sm + BT * PAD;                    // BT*PAD
    float* P2 = sm + 2 * BT * PAD;                // BT*PADP (P duplicated pairs)
    float* CV = sm + 2 * BT * PAD + BT * PADP;    // 64

    const int b   = blockIdx.y;
    const int it  = blockIdx.x;
    const float* xb = x + (size_t)b * TT * DD;
    const int tid = threadIdx.x;
    const int g   = tid >> 4, l16 = tid & 15;
    const int i0  = g * 4;
    const int d0  = l16 * 4;

#pragma unroll
    for (int k = 0; k < 4; k++) {
        int idx = tid + k * 256;
        int r = idx >> 4, c4 = (idx & 15) * 4;
        *(float4*)&XI[r * PAD + c4] = *(const float4*)&xb[(it * BT + r) * DD + c4];
    }

    f2 o[4][2];
#pragma unroll
    for (int r = 0; r < 4; r++) { o[r][0] = 0ull; o[r][1] = 0ull; }

    for (int jt = 0; jt < NT; jt++) {
        __syncthreads();  // previous PV done reading XJ/P2
#pragma unroll
        for (int k = 0; k < 4; k++) {
            int idx = tid + k * 256;
            int r = idx >> 4, c4 = (idx & 15) * 4;
            *(float4*)&XJ[r * PAD + c4] = *(const float4*)&xb[(jt * BT + r) * DD + c4];
        }
        if (tid < 16)
            *(float4*)&CV[tid * 4] = *(const float4*)&g_c[b * TT + jt * BT + tid * 4];
        __syncthreads();

        // S tile
        f2 acc[4][4];
#pragma unroll
        for (int r = 0; r < 4; r++)
#pragma unroll
            for (int c = 0; c < 4; c++) acc[r][c] = 0ull;

#pragma unroll
        for (int d = 0; d < DD; d += 4) {
            ulonglong2 av[4], bv[4];
#pragma unroll
            for (int r = 0; r < 4; r++)
                av[r] = *(const ulonglong2*)&XI[(i0 + r) * PAD + d];
#pragma unroll
            for (int c = 0; c < 4; c++)
                bv[c] = *(const ulonglong2*)&XJ[(l16 + 16 * c) * PAD + d];
#pragma unroll
            for (int r = 0; r < 4; r++)
#pragma unroll
                for (int c = 0; c < 4; c++) {
                    fma2(acc[r][c], av[r].x, bv[c].x);
                    fma2(acc[r][c], av[r].y, bv[c].y);
                }
        }

        // P = exp(S - c_j), stored duplicated (p,p) for packed PV
#pragma unroll
        for (int r = 0; r < 4; r++)
#pragma unroll
            for (int c = 0; c < 4; c++) {
                int jc = l16 + 16 * c;
                float p = __expf(f2hadd(acc[r][c]) - CV[jc]);
                *(f2*)&P2[(i0 + r) * PADP + 2 * jc] = f2dup(p);
            }
        __syncthreads();

        // O += P @ XJ  (packed along d-pairs)
#pragma unroll 4
        for (int j = 0; j < BT; j += 4) {
            ulonglong2 xv[4];
#pragma unroll
            for (int q = 0; q < 4; q++)
                xv[q] = *(const ulonglong2*)&XJ[(j + q) * PAD + d0];
#pragma unroll
            for (int r = 0; r < 4; r++) {
                ulonglong2 u0 = *(const ulonglong2*)&P2[(i0 + r) * PADP + 2 * j];
                ulonglong2 u1 = *(const ulonglong2*)&P2[(i0 + r) * PADP + 2 * j + 4];
                fma2(o[r][0], u0.x, xv[0].x); fma2(o[r][1], u0.x, xv[0].y);
                fma2(o[r][0], u0.y, xv[1].x); fma2(o[r][1], u0.y, xv[1].y);
                fma2(o[r][0], u1.x, xv[2].x); fma2(o[r][1], u1.x, xv[2].y);
                fma2(o[r][0], u1.y, xv[3].x); fma2(o[r][1], u1.y, xv[3].y);
            }
        }
    }

    // transpose epilogue: [i,d] -> [d,i] through smem, coalesced store
    __syncthreads();
    float* Ot = P2;  // reuse, logical stride 65
#pragma unroll
    for (int r = 0; r < 4; r++) {
        float2 a = f2unpack(o[r][0]);
        float2 c = f2unpack(o[r][1]);
        Ot[(d0 + 0) * 65 + i0 + r] = a.x;
        Ot[(d0 + 1) * 65 + i0 + r] = a.y;
        Ot[(d0 + 2) * 65 + i0 + r] = c.x;
        Ot[(d0 + 3) * 65 + i0 + r] = c.y;
    }
    __syncthreads();
    float* ob = out + (size_t)b * DD * TT + it * BT;
#pragma unroll
    for (int k = 0; k < 4; k++) {
        int idx = tid + k * 256;
        int d = idx >> 4, q4 = (idx & 15) * 4;
        float4 v = make_float4(Ot[d * 65 + q4 + 0], Ot[d * 65 + q4 + 1],
                               Ot[d * 65 + q4 + 2], Ot[d * 65 + q4 + 3]);
        *(float4*)&ob[(size_t)d * TT + q4] = v;
    }
}

extern "C" void kernel_launch(void* const* d_in, const int* in_sizes, int n_in,
                              void* d_out, int out_size) {
    (void)in_sizes; (void)n_in; (void)out_size;
    const float* x = (const float*)d_in[0];
    float* out = (float*)d_out;

    const int smem2 = (2 * BT * PAD + BT * PADP + 64) * (int)sizeof(float);  // 69888 B
    cudaFuncSetAttribute(out_kernel, cudaFuncAttributeMaxDynamicSharedMemorySize, smem2);

    dim3 grid(NT, 2);
    stats_kernel<<<grid, 256>>>(x);
    out_kernel<<<grid, 256, smem2>>>(x, out);
}

// round 3
// speedup vs baseline: 2.1643x; 1.2974x over previous
#include <cuda_runtime.h>

#define TT 8192
#define DD 64
#define NT 128   // number of 64-wide tiles along T

typedef unsigned long long f2;

__device__ __forceinline__ void fma2(f2& d, f2 a, f2 b) {
    asm("fma.rn.f32x2 %0, %1, %2, %0;" : "+l"(d) : "l"(a), "l"(b));
}
__device__ __forceinline__ float2 f2unpack(f2 v) {
    float2 f;
    asm("mov.b64 {%0, %1}, %2;" : "=f"(f.x), "=f"(f.y) : "l"(v));
    return f;
}

// scratch
__device__ float g_w[2 * TT];                 // 1 / sum_i exp(S[i,j]-100)
__device__ float g_xt[2 * DD * TT];           // x transposed: [b][d][t]
__device__ float g_p[2ull * TT * TT];         // exp(S-100), fp32 (512 MiB)

// XOR-swizzled transposed-X tile offset: row d (64 floats), 16B chunks XORed by d>>2.
// Conflict-free for row-major stores and for column-strided LDS.128 reads.
__device__ __forceinline__ int xoff(int d, int j) {
    return d * 64 + ((((j >> 2) ^ (d >> 2)) & 15) << 2) + (j & 3);
}

// ---------------------------------------------------------------------------
// k0: transpose x into g_xt (4 MB, L2-resident afterwards)
// ---------------------------------------------------------------------------
__global__ void __launch_bounds__(256) k0_transpose(const float* __restrict__ x) {
    __shared__ float t[64 * 65];
    const int b = blockIdx.y, it = blockIdx.x, tid = threadIdx.x;
    const float* xb = x + (size_t)b * TT * DD;
#pragma unroll
    for (int k = 0; k < 4; k++) {
        int m = k * 256 + tid, r = m >> 4, c4 = (m & 15) * 4;
        float4 v = *(const float4*)&xb[(it * 64 + r) * DD + c4];
        t[(c4 + 0) * 65 + r] = v.x;
        t[(c4 + 1) * 65 + r] = v.y;
        t[(c4 + 2) * 65 + r] = v.z;
        t[(c4 + 3) * 65 + r] = v.w;
    }
    __syncthreads();
#pragma unroll
    for (int k = 0; k < 16; k++) {
        int m = k * 256 + tid, d = m >> 6, i = m & 63;
        g_xt[((size_t)b * DD + d) * TT + it * 64 + i] = t[d * 65 + i];
    }
}

// ---------------------------------------------------------------------------
// k1: per 64-row strip — S = XI @ X^T, P~ = exp(S-100) streamed to g_p,
//     w_j = 1/sum. N-packed f32x2 GEMM (acc f2 = two adjacent j's).
// ---------------------------------------------------------------------------
__global__ void __launch_bounds__(256, 2) k1_score(const float* __restrict__ x) {
    __shared__ float XID[64 * 132];   // duplicated XI: XID[i*132 + 2d{,+1}] = x[i][d]
    __shared__ float XJT[64 * 64];    // swizzled transposed X tile
    const int b = blockIdx.y, it = blockIdx.x, tid = threadIdx.x;
    const int ti = tid >> 4, tj = tid & 15;
    const int i0 = ti * 4, j0 = tj * 4;
    const float* xb = x + (size_t)b * TT * DD;

#pragma unroll
    for (int k = 0; k < 4; k++) {
        int m = k * 256 + tid, r = m >> 4, c4 = (m & 15) * 4;
        float4 v = *(const float4*)&xb[(it * 64 + r) * DD + c4];
        *(float4*)&XID[r * 132 + 2 * c4]     = make_float4(v.x, v.x, v.y, v.y);
        *(float4*)&XID[r * 132 + 2 * c4 + 4] = make_float4(v.z, v.z, v.w, v.w);
    }

    float l[4] = {0.f, 0.f, 0.f, 0.f};

    // prefetch tile 0 of X^T
    float4 nxt[4];
#pragma unroll
    for (int k = 0; k < 4; k++) {
        int m = k * 256 + tid, d = m >> 4, c4 = (m & 15) * 4;
        nxt[k] = *(const float4*)&g_xt[((size_t)b * DD + d) * TT + c4];
    }

    for (int jt = 0; jt < NT; jt++) {
        __syncthreads();
#pragma unroll
        for (int k = 0; k < 4; k++) {
            int m = k * 256 + tid, d = m >> 4, c4 = (m & 15) * 4;
            *(float4*)&XJT[xoff(d, c4)] = nxt[k];
        }
        __syncthreads();
        if (jt + 1 < NT) {
#pragma unroll
            for (int k = 0; k < 4; k++) {
                int m = k * 256 + tid, d = m >> 4, c4 = (m & 15) * 4;
                nxt[k] = *(const float4*)&g_xt[((size_t)b * DD + d) * TT + (jt + 1) * 64 + c4];
            }
        }

        f2 acc[4][2];
#pragma unroll
        for (int r = 0; r < 4; r++) { acc[r][0] = 0ull; acc[r][1] = 0ull; }

#pragma unroll 8
        for (int d = 0; d < DD; d += 2) {
            ulonglong2 b0 = *(const ulonglong2*)&XJT[xoff(d, j0)];
            ulonglong2 b1 = *(const ulonglong2*)&XJT[xoff(d + 1, j0)];
#pragma unroll
            for (int r = 0; r < 4; r++) {
                ulonglong2 a = *(const ulonglong2*)&XID[(i0 + r) * 132 + 2 * d];
                fma2(acc[r][0], a.x, b0.x); fma2(acc[r][1], a.x, b0.y);
                fma2(acc[r][0], a.y, b1.x); fma2(acc[r][1], a.y, b1.y);
            }
        }

#pragma unroll
        for (int r = 0; r < 4; r++) {
            float2 s0 = f2unpack(acc[r][0]);
            float2 s1 = f2unpack(acc[r][1]);
            float p0 = __expf(s0.x - 100.f), p1 = __expf(s0.y - 100.f);
            float p2 = __expf(s1.x - 100.f), p3 = __expf(s1.y - 100.f);
            *(float4*)&g_p[((size_t)b * TT + it * 64 + i0 + r) * TT + (size_t)jt * 64 + j0] =
                make_float4(p0, p1, p2, p3);
            l[r] += (p0 + p1) + (p2 + p3);
        }
    }

#pragma unroll
    for (int r = 0; r < 4; r++) {
#pragma unroll
        for (int w = 1; w < 16; w <<= 1)
            l[r] += __shfl_xor_sync(0xffffffffu, l[r], w);
        if (tj == 0) g_w[b * TT + it * 64 + i0 + r] = 1.0f / l[r];
    }
}

// ---------------------------------------------------------------------------
// k2: out[i,d] = sum_j P~[i,j] * (w_j * x[j,d]); K(=j)-packed f32x2, output [B,D,T]
// ---------------------------------------------------------------------------
__global__ void __launch_bounds__(256, 2) k2_pv(float* __restrict__ out) {
    __shared__ float P[64 * 68];      // P~ tile, row-major
    __shared__ float XJT[64 * 64];    // swizzled transposed, pre-scaled by w_j
    const int b = blockIdx.y, it = blockIdx.x, tid = threadIdx.x;
    const int ti = tid >> 4, td = tid & 15;
    const int i0 = ti * 4, d0 = td * 4;
    const int c4 = (tid & 15) * 4;    // fixed column group for loader lanes

    f2 o[4][4];
#pragma unroll
    for (int r = 0; r < 4; r++)
#pragma unroll
        for (int c = 0; c < 4; c++) o[r][c] = 0ull;

    float4 np[4], nx[4], nw;
    // prefetch tile 0
#pragma unroll
    for (int k = 0; k < 4; k++) {
        int m = k * 256 + tid;
        int pr = m >> 4;
        np[k] = *(const float4*)&g_p[((size_t)b * TT + it * 64 + pr) * TT + c4];
        nx[k] = *(const float4*)&g_xt[((size_t)b * DD + (m >> 4)) * TT + c4];
    }
    nw = *(const float4*)&g_w[b * TT + c4];

    for (int jt = 0; jt < NT; jt++) {
        __syncthreads();
#pragma unroll
        for (int k = 0; k < 4; k++) {
            int m = k * 256 + tid, rr = m >> 4;
            *(float4*)&P[rr * 68 + c4] = np[k];
            float4 v = nx[k];
            v.x *= nw.x; v.y *= nw.y; v.z *= nw.z; v.w *= nw.w;
            *(float4*)&XJT[xoff(rr, c4)] = v;
        }
        __syncthreads();
        if (jt + 1 < NT) {
#pragma unroll
            for (int k = 0; k < 4; k++) {
                int m = k * 256 + tid, rr = m >> 4;
                np[k] = *(const float4*)&g_p[((size_t)b * TT + it * 64 + rr) * TT +
                                             (size_t)(jt + 1) * 64 + c4];
                nx[k] = *(const float4*)&g_xt[((size_t)b * DD + rr) * TT + (jt + 1) * 64 + c4];
            }
            nw = *(const float4*)&g_w[b * TT + (jt + 1) * 64 + c4];
        }

#pragma unroll 4
        for (int j = 0; j < 64; j += 4) {
            ulonglong2 xv[4], pv[4];
#pragma unroll
            for (int c = 0; c < 4; c++)
                xv[c] = *(const ulonglong2*)&XJT[xoff(d0 + c, j)];
#pragma unroll
            for (int r = 0; r < 4; r++)
                pv[r] = *(const ulonglong2*)&P[(i0 + r) * 68 + j];
#pragma unroll
            for (int r = 0; r < 4; r++)
#pragma unroll
                for (int c = 0; c < 4; c++) {
                    fma2(o[r][c], pv[r].x, xv[c].x);
                    fma2(o[r][c], pv[r].y, xv[c].y);
                }
        }
    }

    // transpose epilogue through smem (reuse P), output [B, D, T]
    __syncthreads();
    float* Ot = P;  // 64*65 <= 64*68
#pragma unroll
    for (int r = 0; r < 4; r++)
#pragma unroll
        for (int c = 0; c < 4; c++) {
            float2 t = f2unpack(o[r][c]);
            Ot[(d0 + c) * 65 + i0 + r] = t.x + t.y;
        }
    __syncthreads();
#pragma unroll
    for (int k = 0; k < 16; k++) {
        int m = k * 256 + tid, d = m >> 6, i = m & 63;
        out[((size_t)b * DD + d) * TT + it * 64 + i] = Ot[d * 65 + i];
    }
}

extern "C" void kernel_launch(void* const* d_in, const int* in_sizes, int n_in,
                              void* d_out, int out_size) {
    (void)in_sizes; (void)n_in; (void)out_size;
    const float* x = (const float*)d_in[0];
    float* out = (float*)d_out;

    dim3 grid(NT, 2);
    k0_transpose<<<grid, 256>>>(x);
    k1_score<<<grid, 256>>>(x);
    k2_pv<<<grid, 256>>>(out);
}